// round 1
// baseline (speedup 1.0000x reference)
#include <cuda_runtime.h>
#include <math.h>

// ---------------------------------------------------------------------------
// Scratch (device globals -- allocation-free per harness rules)
// ---------------------------------------------------------------------------
__device__ float  g_col[44236800];   // im2col scratch (max: conv1 75*589824)
__device__ float  g_b1[18874368];    // conv1 out 32*768*768
__device__ float  g_b2[4718592];     // conv2 out 32*384*384
__device__ float  g_b3[9437184];     // conv3 out 64*384*384
__device__ float  g_b4[4718592];     // conv4 out 128*192*192
__device__ float  g_b5[4718592];     // conv5 out
__device__ float  g_b6[4718592];     // conv6 out (attention input)
__device__ float  g_fgp[10616832];   // 1152 x 9216
__device__ float  g_bgp[10616832];   // 1152 x 9216
__device__ float  g_S[84934656];     // 9216 x 9216 (S, then softmaxed A in-place)
__device__ float  g_Rt[10616832];    // 9216 x 1152 (R transposed: [p][c*9+k])
__device__ float  g_attn[4718592];   // attention out 128*192*192
__device__ float  g_b7[4718592];     // conv7 out
__device__ float  g_wt[147456];      // transposed weights (K x OC), max 1152*128
__device__ double g_sumsq;           // Frobenius norm accumulator

// ---------------------------------------------------------------------------
// Helpers
// ---------------------------------------------------------------------------
__device__ __forceinline__ int refl(int i, int n) {
    if (i < 0) i = -i;
    if (i >= n) i = 2 * n - 2 - i;
    return i;
}

__global__ void transpose_w_kernel(const float* __restrict__ w, float* __restrict__ wt,
                                   int OC, int K) {
    int idx = blockIdx.x * blockDim.x + threadIdx.x;
    if (idx >= OC * K) return;
    int oc = idx / K, k = idx % K;
    wt[k * OC + oc] = w[idx];
}

// im2col with reflect padding (matches jnp.pad mode='reflect')
__global__ void im2col_kernel(const float* __restrict__ in, float* __restrict__ col,
                              int C, int H, int W, int KS, int pad, int stride,
                              int OH, int OW) {
    int total = C * KS * KS * OH * OW;
    int idx = blockIdx.x * blockDim.x + threadIdx.x;
    if (idx >= total) return;
    int hw  = OH * OW;
    int pix = idx % hw;
    int row = idx / hw;
    int kx = row % KS;
    int ky = (row / KS) % KS;
    int c  = row / (KS * KS);
    int oy = pix / OW, ox = pix % OW;
    int iy = refl(oy * stride + ky - pad, H);
    int ix = refl(ox * stride + kx - pad, W);
    col[idx] = in[(size_t)c * H * W + (size_t)iy * W + ix];
}

// ---------------------------------------------------------------------------
// SGEMM: C[m,n] = sum_k A(k,m) * B(k,n)
//   NT==0: A stored (K x M) row-major, B stored (K x N) row-major   ("TN")
//   NT==1: A stored (M x K) row-major, B stored (N x K) row-major   ("NT")
// ACT: 0 none, 1 elu, 2 relu. HB: add bias[m].
// 128x128 tile, KT=8, 256 threads, 8x8 microtile.
// ---------------------------------------------------------------------------
template <int ACT, int NT, int HB>
__global__ __launch_bounds__(256, 2) void sgemm_kernel(
    const float* __restrict__ A, const float* __restrict__ B,
    const float* __restrict__ bias, float* __restrict__ C,
    int M, int N, int K) {
    __shared__ __align__(16) float As[8][132];
    __shared__ __align__(16) float Bs[8][132];
    int t  = threadIdx.x;
    int tx = t & 15, ty = t >> 4;
    int m0 = blockIdx.y * 128, n0 = blockIdx.x * 128;

    float acc[8][8];
#pragma unroll
    for (int i = 0; i < 8; i++)
#pragma unroll
        for (int j = 0; j < 8; j++) acc[i][j] = 0.f;

    for (int k0 = 0; k0 < K; k0 += 8) {
        if (!NT) {
#pragma unroll
            for (int i = 0; i < 4; i++) {
                int idx = t + i * 256;
                int kk = idx >> 7, mm = idx & 127;
                int gk = k0 + kk;
                As[kk][mm] = (gk < K && m0 + mm < M) ? A[(size_t)gk * M + m0 + mm] : 0.f;
                Bs[kk][mm] = (gk < K && n0 + mm < N) ? B[(size_t)gk * N + n0 + mm] : 0.f;
            }
        } else {
#pragma unroll
            for (int i = 0; i < 4; i++) {
                int idx = t + i * 256;
                int kk = idx & 7, mm = idx >> 3;
                int gk = k0 + kk;
                As[kk][mm] = (gk < K && m0 + mm < M) ? A[(size_t)(m0 + mm) * K + gk] : 0.f;
                Bs[kk][mm] = (gk < K && n0 + mm < N) ? B[(size_t)(n0 + mm) * K + gk] : 0.f;
            }
        }
        __syncthreads();
#pragma unroll
        for (int kk = 0; kk < 8; kk++) {
            float a[8], b[8];
            *(float4*)&a[0] = *(const float4*)&As[kk][ty * 8];
            *(float4*)&a[4] = *(const float4*)&As[kk][ty * 8 + 4];
            *(float4*)&b[0] = *(const float4*)&Bs[kk][tx * 8];
            *(float4*)&b[4] = *(const float4*)&Bs[kk][tx * 8 + 4];
#pragma unroll
            for (int i = 0; i < 8; i++)
#pragma unroll
                for (int j = 0; j < 8; j++) acc[i][j] += a[i] * b[j];
        }
        __syncthreads();
    }

#pragma unroll
    for (int i = 0; i < 8; i++) {
        int gm = m0 + ty * 8 + i;
        if (gm >= M) continue;
        float bv = HB ? bias[gm] : 0.f;
#pragma unroll
        for (int j = 0; j < 8; j++) {
            int gn = n0 + tx * 8 + j;
            if (gn >= N) continue;
            float v = acc[i][j] + bv;
            if (ACT == 1) v = v > 0.f ? v : expm1f(v);
            else if (ACT == 2) v = fmaxf(v, 0.f);
            C[(size_t)gm * N + gn] = v;
        }
    }
}

// ---------------------------------------------------------------------------
// Attention: fused downsample(::2) + mask + zero-pad 3x3 patch extraction.
// fgp/bgp are (1152, 9216) = (C*9, 96*96), row = c*9 + dy*3 + dx.
// ---------------------------------------------------------------------------
__global__ void patches_kernel(const float* __restrict__ x6, const float* __restrict__ mask,
                               float* __restrict__ fgp, float* __restrict__ bgp) {
    int idx = blockIdx.x * blockDim.x + threadIdx.x;
    if (idx >= 1152 * 9216) return;
    int p   = idx % 9216;
    int row = idx / 9216;
    int k = row % 9, c = row / 9;
    int dy = k / 3, dx = k % 3;
    int py = p / 96, px = p % 96;
    int sy = py + dy - 1, sx = px + dx - 1;
    float v = 0.f, f = 0.f;
    if (sy >= 0 && sy < 96 && sx >= 0 && sx < 96) {
        v = x6[c * 36864 + (2 * sy) * 192 + 2 * sx];
        f = v * mask[(2 * sy) * 192 + 2 * sx];
    }
    bgp[idx] = v;
    fgp[idx] = f;
}

__global__ void zero_sum_kernel() {
    if (threadIdx.x == 0 && blockIdx.x == 0) g_sumsq = 0.0;
}

__global__ void sumsq_kernel(const float* __restrict__ S, int n) {
    float s = 0.f;
    for (int i = blockIdx.x * blockDim.x + threadIdx.x; i < n; i += gridDim.x * blockDim.x) {
        float v = S[i];
        s += v * v;
    }
    for (int o = 16; o; o >>= 1) s += __shfl_down_sync(0xffffffffu, s, o);
    __shared__ float red[32];
    int lane = threadIdx.x & 31, w = threadIdx.x >> 5;
    if (lane == 0) red[w] = s;
    __syncthreads();
    if (w == 0) {
        s = (lane < (int)(blockDim.x >> 5)) ? red[lane] : 0.f;
        for (int o = 16; o; o >>= 1) s += __shfl_down_sync(0xffffffffu, s, o);
        if (lane == 0) atomicAdd(&g_sumsq, (double)s);
    }
}

// One block per row p: A[p,:] = softmax(scale * S[p,:]), scale = 10/nrm. In-place.
__global__ void softmax_kernel(float* __restrict__ S) {
    extern __shared__ float row[];  // 9216 floats
    __shared__ float red[8];
    __shared__ float bval;
    int p = blockIdx.x;
    float* Sr = S + (size_t)p * 9216;
    float nrm = fmaxf(sqrtf((float)g_sumsq), 1e-12f);
    float scale = 10.f / nrm;
    int t = threadIdx.x;
    int lane = t & 31, w = t >> 5;

    float lm = -INFINITY;
    for (int i = t; i < 9216; i += 256) {
        float v = Sr[i] * scale;
        row[i] = v;
        lm = fmaxf(lm, v);
    }
    for (int o = 16; o; o >>= 1) lm = fmaxf(lm, __shfl_xor_sync(0xffffffffu, lm, o));
    if (lane == 0) red[w] = lm;
    __syncthreads();
    if (t < 32) {
        float v = (t < 8) ? red[t] : -INFINITY;
        for (int o = 4; o; o >>= 1) v = fmaxf(v, __shfl_xor_sync(0xffffffffu, v, o));
        if (t == 0) bval = v;
    }
    __syncthreads();
    float mx = bval;

    float ls = 0.f;
    for (int i = t; i < 9216; i += 256) {
        float e = __expf(row[i] - mx);
        row[i] = e;
        ls += e;
    }
    for (int o = 16; o; o >>= 1) ls += __shfl_xor_sync(0xffffffffu, ls, o);
    __syncthreads();
    if (lane == 0) red[w] = ls;
    __syncthreads();
    if (t < 32) {
        float v = (t < 8) ? red[t] : 0.f;
        for (int o = 4; o; o >>= 1) v += __shfl_xor_sync(0xffffffffu, v, o);
        if (t == 0) bval = v;
    }
    __syncthreads();
    float inv = 1.f / bval;
    for (int i = t; i < 9216; i += 256) Sr[i] = row[i] * inv;
}

// Overlap-add fold (crop [1:97]) + mask + 2x nearest upsample.
// Rt layout: [p][c*9 + dy*3 + dx], p = py*96+px.
__global__ void fold_kernel(const float* __restrict__ Rt, const float* __restrict__ mask,
                            float* __restrict__ attn) {
    int idx = blockIdx.x * blockDim.x + threadIdx.x;
    if (idx >= 128 * 9216) return;
    int c  = idx / 9216;
    int rem = idx % 9216;
    int yy = rem / 96, xx = rem % 96;
    float s = 0.f;
#pragma unroll
    for (int dy = 0; dy < 3; dy++) {
        int py = yy + 1 - dy;
        if (py < 0 || py >= 96) continue;
#pragma unroll
        for (int dx = 0; dx < 3; dx++) {
            int px = xx + 1 - dx;
            if (px < 0 || px >= 96) continue;
            s += Rt[(size_t)(py * 96 + px) * 1152 + c * 9 + dy * 3 + dx];
        }
    }
    s *= mask[(2 * yy) * 192 + 2 * xx];
    size_t base = (size_t)c * 36864 + (size_t)(2 * yy) * 192 + 2 * xx;
    attn[base]       = s;
    attn[base + 1]   = s;
    attn[base + 192] = s;
    attn[base + 193] = s;
}

// ---------------------------------------------------------------------------
// Host orchestration
// ---------------------------------------------------------------------------
static void run_conv(const float* in, float* out, const float* w, const float* bias,
                     float* col, float* wt,
                     int C, int H, int W, int OC, int KS, int pad, int stride, int act) {
    int OH = (H + 2 * pad - KS) / stride + 1;
    int OW = (W + 2 * pad - KS) / stride + 1;
    int K = C * KS * KS, N = OH * OW, M = OC;
    int wn = OC * K;
    transpose_w_kernel<<<(wn + 255) / 256, 256>>>(w, wt, OC, K);
    int total = K * N;
    im2col_kernel<<<(total + 255) / 256, 256>>>(in, col, C, H, W, KS, pad, stride, OH, OW);
    dim3 grid((N + 127) / 128, (M + 127) / 128);
    if (act == 1)
        sgemm_kernel<1, 0, 1><<<grid, 256>>>(wt, col, bias, out, M, N, K);
    else
        sgemm_kernel<2, 0, 1><<<grid, 256>>>(wt, col, bias, out, M, N, K);
}

extern "C" void kernel_launch(void* const* d_in, const int* in_sizes, int n_in,
                              void* d_out, int out_size) {
    const float* x    = (const float*)d_in[0];
    const float* mask = (const float*)d_in[1];
    const float* w[8];
    const float* b[8];
    for (int i = 0; i < 8; i++) {
        w[i] = (const float*)d_in[2 + 2 * i];
        b[i] = (const float*)d_in[3 + 2 * i];
    }

    float *col, *b1, *b2, *b3, *b4, *b5, *b6, *fgp, *bgp, *S, *Rt, *attn, *b7, *wt;
    cudaGetSymbolAddress((void**)&col,  g_col);
    cudaGetSymbolAddress((void**)&b1,   g_b1);
    cudaGetSymbolAddress((void**)&b2,   g_b2);
    cudaGetSymbolAddress((void**)&b3,   g_b3);
    cudaGetSymbolAddress((void**)&b4,   g_b4);
    cudaGetSymbolAddress((void**)&b5,   g_b5);
    cudaGetSymbolAddress((void**)&b6,   g_b6);
    cudaGetSymbolAddress((void**)&fgp,  g_fgp);
    cudaGetSymbolAddress((void**)&bgp,  g_bgp);
    cudaGetSymbolAddress((void**)&S,    g_S);
    cudaGetSymbolAddress((void**)&Rt,   g_Rt);
    cudaGetSymbolAddress((void**)&attn, g_attn);
    cudaGetSymbolAddress((void**)&b7,   g_b7);
    cudaGetSymbolAddress((void**)&wt,   g_wt);

    // Encoder
    run_conv(x,  b1, w[0], b[0], col, wt,   3, 768, 768,  32, 5, 2, 1, 1);
    run_conv(b1, b2, w[1], b[1], col, wt,  32, 768, 768,  32, 3, 1, 2, 1);
    run_conv(b2, b3, w[2], b[2], col, wt,  32, 384, 384,  64, 3, 1, 1, 1);
    run_conv(b3, b4, w[3], b[3], col, wt,  64, 384, 384, 128, 3, 1, 2, 1);
    run_conv(b4, b5, w[4], b[4], col, wt, 128, 192, 192, 128, 3, 1, 1, 1);
    run_conv(b5, b6, w[5], b[5], col, wt, 128, 192, 192, 128, 3, 1, 1, 2);  // relu

    // Contextual attention
    patches_kernel<<<(1152 * 9216 + 255) / 256, 256>>>(b6, mask, fgp, bgp);
    {
        dim3 g(72, 72);  // S = fgp^T * bgp : (9216 x 9216), K=1152, TN
        sgemm_kernel<0, 0, 0><<<g, 256>>>(fgp, bgp, nullptr, S, 9216, 9216, 1152);
    }
    zero_sum_kernel<<<1, 32>>>();
    sumsq_kernel<<<2048, 256>>>(S, 84934656);
    softmax_kernel<<<9216, 256, 9216 * sizeof(float)>>>(S);
    {
        dim3 g(9, 72);   // Rt[p,c] = sum_q A[p,q]*bgp[c,q] : M=9216, N=1152, K=9216, NT
        sgemm_kernel<0, 1, 0><<<g, 256>>>(S, bgp, nullptr, Rt, 9216, 1152, 9216);
    }
    fold_kernel<<<(128 * 9216 + 255) / 256, 256>>>(Rt, mask, attn);

    // Decoder head
    run_conv(attn, b7,            w[6], b[6], col, wt, 128, 192, 192, 128, 3, 1, 1, 1);
    run_conv(b7, (float*)d_out,   w[7], b[7], col, wt, 128, 192, 192, 128, 3, 1, 1, 1);
}

// round 3
// speedup vs baseline: 1.3594x; 1.3594x over previous
#include <cuda_runtime.h>
#include <stdint.h>
#include <cstdint>
#include <math.h>

// ---------------------------------------------------------------------------
// Scratch (device globals -- allocation-free per harness rules)
// ---------------------------------------------------------------------------
__device__ float  g_col[44236800];   // im2col scratch (max: conv1 75*589824)
__device__ float  g_b1[18874368];    // conv1 out 32*768*768
__device__ float  g_b2[4718592];    // conv2 out 32*384*384
__device__ float  g_b3[9437184];    // conv3 out 64*384*384
__device__ float  g_b4[4718592];    // conv4 out 128*192*192
__device__ float  g_b5[4718592];    // conv5 out
__device__ float  g_b6[4718592];    // conv6 out (attention input)
__device__ float  g_fgp[10616832];  // 1152 x 9216   (K x M for S)
__device__ float  g_bgp[10616832];  // 1152 x 9216   (K x N for S; N x K for R)
__device__ float  g_S[84934656];    // 9216 x 9216 (S, then softmaxed A in-place)
__device__ float  g_Rt[10616832];   // 9216 x 1152 (R transposed: [p][c*9+k])
__device__ float  g_attn[4718592];  // attention out 128*192*192
__device__ float  g_b7[4718592];    // conv7 out
__device__ double g_sumsq;          // Frobenius norm accumulator

// ---------------------------------------------------------------------------
// Helpers
// ---------------------------------------------------------------------------
__device__ __forceinline__ int refl(int i, int n) {
    if (i < 0) i = -i;
    if (i >= n) i = 2 * n - 2 - i;
    return i;
}

__device__ __forceinline__ unsigned f2tf32(float x) {
    unsigned r;
    asm("cvt.rna.tf32.f32 %0, %1;" : "=r"(r) : "f"(x));
    return r;
}

__device__ __forceinline__ void mma_tf32(float* c, const unsigned* a, unsigned b0, unsigned b1) {
    asm volatile(
        "mma.sync.aligned.m16n8k8.row.col.f32.tf32.tf32.f32 "
        "{%0,%1,%2,%3},{%4,%5,%6,%7},{%8,%9},{%0,%1,%2,%3};\n"
        : "+f"(c[0]), "+f"(c[1]), "+f"(c[2]), "+f"(c[3])
        : "r"(a[0]), "r"(a[1]), "r"(a[2]), "r"(a[3]), "r"(b0), "r"(b1));
}

// im2col with reflect padding (matches jnp.pad mode='reflect')
__global__ void im2col_kernel(const float* __restrict__ in, float* __restrict__ col,
                              int C, int H, int W, int KS, int pad, int stride,
                              int OH, int OW) {
    int total = C * KS * KS * OH * OW;
    int idx = blockIdx.x * blockDim.x + threadIdx.x;
    if (idx >= total) return;
    int hw  = OH * OW;
    int pix = idx % hw;
    int row = idx / hw;
    int kx = row % KS;
    int ky = (row / KS) % KS;
    int c  = row / (KS * KS);
    int oy = pix / OW, ox = pix % OW;
    int iy = refl(oy * stride + ky - pad, H);
    int ix = refl(ox * stride + kx - pad, W);
    col[idx] = in[(size_t)c * H * W + (size_t)iy * W + ix];
}

// ---------------------------------------------------------------------------
// FFMA SGEMM for convs: C[m,n] = act(sum_k A[m,k] * B[k,n] + bias[m])
//   A stored M x K row-major (weights), B stored K x N row-major (im2col).
// ACT: 1 elu, 2 relu. 128x128 tile, KT=8, 256 threads, 8x8 microtile.
// ---------------------------------------------------------------------------
template <int ACT>
__global__ __launch_bounds__(256, 2) void sgemm_kernel(
    const float* __restrict__ A, const float* __restrict__ B,
    const float* __restrict__ bias, float* __restrict__ C,
    int M, int N, int K) {
    __shared__ __align__(16) float As[8][132];
    __shared__ __align__(16) float Bs[8][132];
    int t  = threadIdx.x;
    int tx = t & 15, ty = t >> 4;
    int m0 = blockIdx.y * 128, n0 = blockIdx.x * 128;

    float acc[8][8];
#pragma unroll
    for (int i = 0; i < 8; i++)
#pragma unroll
        for (int j = 0; j < 8; j++) acc[i][j] = 0.f;

    for (int k0 = 0; k0 < K; k0 += 8) {
        // A: M x K, tile 128m x 8k
#pragma unroll
        for (int i = 0; i < 4; i++) {
            int idx = t + i * 256;
            int kk = idx & 7, mm = idx >> 3;
            int gk = k0 + kk;
            As[kk][mm] = (gk < K && m0 + mm < M) ? A[(size_t)(m0 + mm) * K + gk] : 0.f;
        }
        // B: K x N, tile 8k x 128n
#pragma unroll
        for (int i = 0; i < 4; i++) {
            int idx = t + i * 256;
            int kk = idx >> 7, mm = idx & 127;
            int gk = k0 + kk;
            Bs[kk][mm] = (gk < K && n0 + mm < N) ? B[(size_t)gk * N + n0 + mm] : 0.f;
        }
        __syncthreads();
#pragma unroll
        for (int kk = 0; kk < 8; kk++) {
            float a[8], b[8];
            *(float4*)&a[0] = *(const float4*)&As[kk][ty * 8];
            *(float4*)&a[4] = *(const float4*)&As[kk][ty * 8 + 4];
            *(float4*)&b[0] = *(const float4*)&Bs[kk][tx * 8];
            *(float4*)&b[4] = *(const float4*)&Bs[kk][tx * 8 + 4];
#pragma unroll
            for (int i = 0; i < 8; i++)
#pragma unroll
                for (int j = 0; j < 8; j++) acc[i][j] += a[i] * b[j];
        }
        __syncthreads();
    }

#pragma unroll
    for (int i = 0; i < 8; i++) {
        int gm = m0 + ty * 8 + i;
        if (gm >= M) continue;
        float bv = bias[gm];
#pragma unroll
        for (int j = 0; j < 8; j++) {
            int gn = n0 + tx * 8 + j;
            if (gn >= N) continue;
            float v = acc[i][j] + bv;
            if (ACT == 1) v = v > 0.f ? v : expm1f(v);
            else v = fmaxf(v, 0.f);
            C[(size_t)gm * N + gn] = v;
        }
    }
}

// ---------------------------------------------------------------------------
// TF32 tensor-core GEMM (mma.sync.m16n8k8).
//   LAYOUT 0 (TN): A stored K x M row-major, B stored K x N row-major.
//   LAYOUT 1 (NT): A stored M x K row-major, B stored N x K row-major.
//   SPLIT 1: fp32-accurate via hi/lo tf32 decomposition (3 mma per product).
// C[m,n] = sum_k a(k,m)*b(k,n), no bias/act. Requires M%128==0, N%128==0, K%16==0.
// Block tile 128x128, KT=16, 8 warps, warp tile 32x64 (2 m-frags x 8 n-frags).
// ---------------------------------------------------------------------------
template <int LAYOUT, int SPLIT>
__global__ __launch_bounds__(256) void mma_gemm_kernel(
    const float* __restrict__ A, const float* __restrict__ B, float* __restrict__ C,
    int M, int N, int K) {
    __shared__ unsigned Asm[SPLIT ? 32 : 16][136];  // rows 16..31 = lo part
    __shared__ unsigned Bsm[SPLIT ? 32 : 16][136];
    int t = threadIdx.x;
    int m0 = blockIdx.y * 128, n0 = blockIdx.x * 128;
    int lane = t & 31, warp = t >> 5;
    int g = lane >> 2, th = lane & 3;
    int wy = warp >> 1, wx = warp & 1;
    int mbase = wy * 32, nbase = wx * 64;

    float acc[2][8][4];
#pragma unroll
    for (int mi = 0; mi < 2; mi++)
#pragma unroll
        for (int ni = 0; ni < 8; ni++)
#pragma unroll
            for (int r = 0; r < 4; r++) acc[mi][ni][r] = 0.f;

    float4 pa[2], pb[2];

    auto load_tile = [&](int k0) {
#pragma unroll
        for (int i = 0; i < 2; i++) {
            int id = t + i * 256;
            if (LAYOUT == 0) {  // K x M / K x N tiles: 16 rows x 128 cols
                int kk = id >> 5, cg = id & 31;
                pa[i] = *(const float4*)&A[(size_t)(k0 + kk) * M + m0 + cg * 4];
                pb[i] = *(const float4*)&B[(size_t)(k0 + kk) * N + n0 + cg * 4];
            } else {            // M x K / N x K tiles: 128 rows x 16 cols
                int mm = id >> 2, kg = id & 3;
                pa[i] = *(const float4*)&A[(size_t)(m0 + mm) * K + k0 + kg * 4];
                pb[i] = *(const float4*)&B[(size_t)(n0 + mm) * K + k0 + kg * 4];
            }
        }
    };

    auto store_tile = [&]() {
#pragma unroll
        for (int i = 0; i < 2; i++) {
            int id = t + i * 256;
            const float* va = (const float*)&pa[i];
            const float* vb = (const float*)&pb[i];
#pragma unroll
            for (int j = 0; j < 4; j++) {
                int kk, cc;
                if (LAYOUT == 0) { kk = id >> 5; cc = (id & 31) * 4 + j; }
                else             { kk = (id & 3) * 4 + j; cc = id >> 2; }
                unsigned ha = f2tf32(va[j]);
                unsigned hb = f2tf32(vb[j]);
                Asm[kk][cc] = ha;
                Bsm[kk][cc] = hb;
                if (SPLIT) {
                    Asm[16 + kk][cc] = f2tf32(va[j] - __uint_as_float(ha));
                    Bsm[16 + kk][cc] = f2tf32(vb[j] - __uint_as_float(hb));
                }
            }
        }
    };

    load_tile(0);
    int nk = K >> 4;
    for (int kt = 0; kt < nk; kt++) {
        __syncthreads();
        store_tile();
        __syncthreads();
        if (kt + 1 < nk) load_tile((kt + 1) << 4);

#pragma unroll
        for (int ks = 0; ks < 16; ks += 8) {
            unsigned ah[2][4], al[2][4];
#pragma unroll
            for (int mi = 0; mi < 2; mi++) {
                int rb = mbase + mi * 16;
                ah[mi][0] = Asm[ks + th][rb + g];
                ah[mi][1] = Asm[ks + th][rb + g + 8];
                ah[mi][2] = Asm[ks + th + 4][rb + g];
                ah[mi][3] = Asm[ks + th + 4][rb + g + 8];
                if (SPLIT) {
                    al[mi][0] = Asm[16 + ks + th][rb + g];
                    al[mi][1] = Asm[16 + ks + th][rb + g + 8];
                    al[mi][2] = Asm[16 + ks + th + 4][rb + g];
                    al[mi][3] = Asm[16 + ks + th + 4][rb + g + 8];
                }
            }
#pragma unroll
            for (int ni = 0; ni < 8; ni++) {
                int cb = nbase + ni * 8;
                unsigned bh0 = Bsm[ks + th][cb + g];
                unsigned bh1 = Bsm[ks + th + 4][cb + g];
#pragma unroll
                for (int mi = 0; mi < 2; mi++) mma_tf32(acc[mi][ni], ah[mi], bh0, bh1);
                if (SPLIT) {
                    unsigned bl0 = Bsm[16 + ks + th][cb + g];
                    unsigned bl1 = Bsm[16 + ks + th + 4][cb + g];
#pragma unroll
                    for (int mi = 0; mi < 2; mi++) {
                        mma_tf32(acc[mi][ni], al[mi], bh0, bh1);
                        mma_tf32(acc[mi][ni], ah[mi], bl0, bl1);
                    }
                }
            }
        }
    }

    // Epilogue: c0,c1 -> (row g, cols 2t,2t+1); c2,c3 -> (row g+8)
#pragma unroll
    for (int mi = 0; mi < 2; mi++) {
        int gm0 = m0 + mbase + mi * 16 + g;
#pragma unroll
        for (int ni = 0; ni < 8; ni++) {
            int gn = n0 + nbase + ni * 8 + 2 * th;
            float2 v0 = {acc[mi][ni][0], acc[mi][ni][1]};
            float2 v1 = {acc[mi][ni][2], acc[mi][ni][3]};
            *(float2*)&C[(size_t)gm0 * N + gn] = v0;
            *(float2*)&C[(size_t)(gm0 + 8) * N + gn] = v1;
        }
    }
}

// ---------------------------------------------------------------------------
// Attention: fused downsample(::2) + mask + zero-pad 3x3 patch extraction.
// fgp/bgp are (1152, 9216) = (C*9, 96*96), row = c*9 + dy*3 + dx.
// ---------------------------------------------------------------------------
__global__ void patches_kernel(const float* __restrict__ x6, const float* __restrict__ mask,
                               float* __restrict__ fgp, float* __restrict__ bgp) {
    int idx = blockIdx.x * blockDim.x + threadIdx.x;
    if (idx >= 1152 * 9216) return;
    int p   = idx % 9216;
    int row = idx / 9216;
    int k = row % 9, c = row / 9;
    int dy = k / 3, dx = k % 3;
    int py = p / 96, px = p % 96;
    int sy = py + dy - 1, sx = px + dx - 1;
    float v = 0.f, f = 0.f;
    if (sy >= 0 && sy < 96 && sx >= 0 && sx < 96) {
        v = x6[c * 36864 + (2 * sy) * 192 + 2 * sx];
        f = v * mask[(2 * sy) * 192 + 2 * sx];
    }
    bgp[idx] = v;
    fgp[idx] = f;
}

__global__ void zero_sum_kernel() {
    if (threadIdx.x == 0 && blockIdx.x == 0) g_sumsq = 0.0;
}

__global__ void sumsq_kernel(const float* __restrict__ S, int n) {
    float s = 0.f;
    for (int i = blockIdx.x * blockDim.x + threadIdx.x; i < n; i += gridDim.x * blockDim.x) {
        float v = S[i];
        s += v * v;
    }
    for (int o = 16; o; o >>= 1) s += __shfl_down_sync(0xffffffffu, s, o);
    __shared__ float red[32];
    int lane = threadIdx.x & 31, w = threadIdx.x >> 5;
    if (lane == 0) red[w] = s;
    __syncthreads();
    if (w == 0) {
        s = (lane < (int)(blockDim.x >> 5)) ? red[lane] : 0.f;
        for (int o = 16; o; o >>= 1) s += __shfl_down_sync(0xffffffffu, s, o);
        if (lane == 0) atomicAdd(&g_sumsq, (double)s);
    }
}

// One block per row p: A[p,:] = softmax(scale * S[p,:]), scale = 10/nrm. In-place.
__global__ void softmax_kernel(float* __restrict__ S) {
    extern __shared__ float row[];  // 9216 floats
    __shared__ float red[8];
    __shared__ float bval;
    int p = blockIdx.x;
    float* Sr = S + (size_t)p * 9216;
    float nrm = fmaxf(sqrtf((float)g_sumsq), 1e-12f);
    float scale = 10.f / nrm;
    int t = threadIdx.x;
    int lane = t & 31, w = t >> 5;

    float lm = -INFINITY;
    for (int i = t; i < 9216; i += 256) {
        float v = Sr[i] * scale;
        row[i] = v;
        lm = fmaxf(lm, v);
    }
    for (int o = 16; o; o >>= 1) lm = fmaxf(lm, __shfl_xor_sync(0xffffffffu, lm, o));
    if (lane == 0) red[w] = lm;
    __syncthreads();
    if (t < 32) {
        float v = (t < 8) ? red[t] : -INFINITY;
        for (int o = 4; o; o >>= 1) v = fmaxf(v, __shfl_xor_sync(0xffffffffu, v, o));
        if (t == 0) bval = v;
    }
    __syncthreads();
    float mx = bval;

    float ls = 0.f;
    for (int i = t; i < 9216; i += 256) {
        float e = __expf(row[i] - mx);
        row[i] = e;
        ls += e;
    }
    for (int o = 16; o; o >>= 1) ls += __shfl_xor_sync(0xffffffffu, ls, o);
    __syncthreads();
    if (lane == 0) red[w] = ls;
    __syncthreads();
    if (t < 32) {
        float v = (t < 8) ? red[t] : 0.f;
        for (int o = 4; o; o >>= 1) v += __shfl_xor_sync(0xffffffffu, v, o);
        if (t == 0) bval = v;
    }
    __syncthreads();
    float inv = 1.f / bval;
    for (int i = t; i < 9216; i += 256) Sr[i] = row[i] * inv;
}

// Overlap-add fold (crop [1:97]) + mask + 2x nearest upsample.
// Rt layout: [p][c*9 + dy*3 + dx], p = py*96+px.
__global__ void fold_kernel(const float* __restrict__ Rt, const float* __restrict__ mask,
                            float* __restrict__ attn) {
    int idx = blockIdx.x * blockDim.x + threadIdx.x;
    if (idx >= 128 * 9216) return;
    int c  = idx / 9216;
    int rem = idx % 9216;
    int yy = rem / 96, xx = rem % 96;
    float s = 0.f;
#pragma unroll
    for (int dy = 0; dy < 3; dy++) {
        int py = yy + 1 - dy;
        if (py < 0 || py >= 96) continue;
#pragma unroll
        for (int dx = 0; dx < 3; dx++) {
            int px = xx + 1 - dx;
            if (px < 0 || px >= 96) continue;
            s += Rt[(size_t)(py * 96 + px) * 1152 + c * 9 + dy * 3 + dx];
        }
    }
    s *= mask[(2 * yy) * 192 + 2 * xx];
    size_t base = (size_t)c * 36864 + (size_t)(2 * yy) * 192 + 2 * xx;
    attn[base]       = s;
    attn[base + 1]   = s;
    attn[base + 192] = s;
    attn[base + 193] = s;
}

// ---------------------------------------------------------------------------
// Host orchestration
// ---------------------------------------------------------------------------
static void run_conv(const float* in, float* out, const float* w, const float* bias,
                     float* col,
                     int C, int H, int W, int OC, int KS, int pad, int stride, int act) {
    int OH = (H + 2 * pad - KS) / stride + 1;
    int OW = (W + 2 * pad - KS) / stride + 1;
    int K = C * KS * KS, N = OH * OW, M = OC;
    int total = K * N;
    im2col_kernel<<<(total + 255) / 256, 256>>>(in, col, C, H, W, KS, pad, stride, OH, OW);
    dim3 grid((N + 127) / 128, (M + 127) / 128);
    if (act == 1)
        sgemm_kernel<1><<<grid, 256>>>(w, col, bias, out, M, N, K);
    else
        sgemm_kernel<2><<<grid, 256>>>(w, col, bias, out, M, N, K);
}

extern "C" void kernel_launch(void* const* d_in, const int* in_sizes, int n_in,
                              void* d_out, int out_size) {
    const float* x    = (const float*)d_in[0];
    const float* mask = (const float*)d_in[1];
    const float* w[8];
    const float* b[8];
    for (int i = 0; i < 8; i++) {
        w[i] = (const float*)d_in[2 + 2 * i];
        b[i] = (const float*)d_in[3 + 2 * i];
    }

    float *col, *b1, *b2, *b3, *b4, *b5, *b6, *fgp, *bgp, *S, *Rt, *attn, *b7;
    cudaGetSymbolAddress((void**)&col,  g_col);
    cudaGetSymbolAddress((void**)&b1,   g_b1);
    cudaGetSymbolAddress((void**)&b2,   g_b2);
    cudaGetSymbolAddress((void**)&b3,   g_b3);
    cudaGetSymbolAddress((void**)&b4,   g_b4);
    cudaGetSymbolAddress((void**)&b5,   g_b5);
    cudaGetSymbolAddress((void**)&b6,   g_b6);
    cudaGetSymbolAddress((void**)&fgp,  g_fgp);
    cudaGetSymbolAddress((void**)&bgp,  g_bgp);
    cudaGetSymbolAddress((void**)&S,    g_S);
    cudaGetSymbolAddress((void**)&Rt,   g_Rt);
    cudaGetSymbolAddress((void**)&attn, g_attn);
    cudaGetSymbolAddress((void**)&b7,   g_b7);

    // Encoder
    run_conv(x,  b1, w[0], b[0], col,   3, 768, 768,  32, 5, 2, 1, 1);
    run_conv(b1, b2, w[1], b[1], col,  32, 768, 768,  32, 3, 1, 2, 1);
    run_conv(b2, b3, w[2], b[2], col,  32, 384, 384,  64, 3, 1, 1, 1);
    run_conv(b3, b4, w[3], b[3], col,  64, 384, 384, 128, 3, 1, 2, 1);
    run_conv(b4, b5, w[4], b[4], col, 128, 192, 192, 128, 3, 1, 1, 1);
    run_conv(b5, b6, w[5], b[5], col, 128, 192, 192, 128, 3, 1, 1, 2);  // relu

    // Contextual attention
    patches_kernel<<<(1152 * 9216 + 255) / 256, 256>>>(b6, mask, fgp, bgp);
    {
        // S = fgp^T * bgp : M=N=9216, K=1152. TN layout, plain tf32
        // (softmax logits ~1e-3 -> tf32 error fully suppressed).
        dim3 g(72, 72);
        mma_gemm_kernel<0, 0><<<g, 256>>>(fgp, bgp, S, 9216, 9216, 1152);
    }
    zero_sum_kernel<<<1, 32>>>();
    sumsq_kernel<<<2048, 256>>>(S, 84934656);
    softmax_kernel<<<9216, 256, 9216 * sizeof(float)>>>(S);
    {
        // Rt[p,c] = sum_q A[p,q]*bgp[c,q] : M=9216, N=1152, K=9216. NT layout,
        // split tf32 (hi/lo) for fp32-level accuracy on the output path.
        dim3 g(9, 72);
        mma_gemm_kernel<1, 1><<<g, 256>>>(S, bgp, Rt, 9216, 1152, 9216);
    }
    fold_kernel<<<(128 * 9216 + 255) / 256, 256>>>(Rt, mask, attn);

    // Decoder head
    run_conv(attn, b7,          w[6], b[6], col, 128, 192, 192, 128, 3, 1, 1, 1);
    run_conv(b7, (float*)d_out, w[7], b[7], col, 128, 192, 192, 128, 3, 1, 1, 1);
}